// round 1
// baseline (speedup 1.0000x reference)
#include <cuda_runtime.h>

// NormmaxBisect, alpha = 1.5, n_iter = 50, d = 2048.
// p = max(x - tau, 0)^2 ; p^alpha = max(x - tau, 0)^3.
// tau in (max-1, max - d^-0.5], so only elements with x > max-1 ever matter.

constexpr int D       = 2048;
constexpr int THREADS = 128;
constexpr int F4S     = D / 4 / THREADS;   // float4 chunks per thread = 4
constexpr int CAND_CAP = 64;
constexpr float TAU_HI_OFF = 0.022097086912079612f;  // (1/2048)^0.5

__global__ void __launch_bounds__(THREADS)
normmax_kernel(const float* __restrict__ X, float* __restrict__ Out)
{
    __shared__ float row[D];
    __shared__ float cand[CAND_CAP];
    __shared__ float s_red[THREADS / 32];
    __shared__ int   s_cnt;
    __shared__ float s_max, s_tau, s_invS;

    const size_t base = (size_t)blockIdx.x * D;
    const float4* __restrict__ xin  = reinterpret_cast<const float4*>(X + base);
    float4* __restrict__       xout = reinterpret_cast<float4*>(Out + base);
    float4* rowv = reinterpret_cast<float4*>(row);

    const int t = threadIdx.x;
    if (t == 0) s_cnt = 0;

    // ---- Pass 1: load row into SMEM, compute block max ----
    float m = -3.402823466e+38f;
#pragma unroll
    for (int k = 0; k < F4S; ++k) {
        float4 v = xin[t + k * THREADS];
        rowv[t + k * THREADS] = v;
        m = fmaxf(m, fmaxf(fmaxf(v.x, v.y), fmaxf(v.z, v.w)));
    }
#pragma unroll
    for (int o = 16; o; o >>= 1)
        m = fmaxf(m, __shfl_xor_sync(0xffffffffu, m, o));
    if ((t & 31) == 0) s_red[t >> 5] = m;
    __syncthreads();
    if (t == 0) {
        float mm = s_red[0];
#pragma unroll
        for (int w = 1; w < THREADS / 32; ++w) mm = fmaxf(mm, s_red[w]);
        s_max = mm;
    }
    __syncthreads();

    const float maxval = s_max;
    const float thresh = maxval - 1.0f;

    // ---- Pass 2: gather candidates (x > max-1) ----
#pragma unroll
    for (int k = 0; k < F4S; ++k) {
        float4 v = rowv[t + k * THREADS];
        if (v.x > thresh) { int p = atomicAdd(&s_cnt, 1); if (p < CAND_CAP) cand[p] = v.x; }
        if (v.y > thresh) { int p = atomicAdd(&s_cnt, 1); if (p < CAND_CAP) cand[p] = v.y; }
        if (v.z > thresh) { int p = atomicAdd(&s_cnt, 1); if (p < CAND_CAP) cand[p] = v.z; }
        if (v.w > thresh) { int p = atomicAdd(&s_cnt, 1); if (p < CAND_CAP) cand[p] = v.w; }
    }
    __syncthreads();

    // ---- Pass 3: bisection, warp 0 only ----
    if (t < 32) {
        const int n  = s_cnt;
        float tau_lo = thresh;
        float dm     = (maxval - TAU_HI_OFF) - tau_lo;
        float tau_m  = tau_lo;

        if (n <= CAND_CAP) {
            // Common path: all 32 lanes redundantly compute the same serial sum
            // over ~12 candidates. No shuffles; branch is trivially uniform.
            for (int it = 0; it < 50; ++it) {
                dm *= 0.5f;
                tau_m = tau_lo + dm;
                if (tau_m == tau_lo) break;   // fp32-frozen: identical to running all 50
                float s0 = 0.f, s1 = 0.f, s2 = 0.f, s3 = 0.f;
                int j = 0;
                for (; j + 4 <= n; j += 4) {
                    float c0 = fmaxf(cand[j]     - tau_m, 0.f); s0 += c0 * c0 * c0;
                    float c1 = fmaxf(cand[j + 1] - tau_m, 0.f); s1 += c1 * c1 * c1;
                    float c2 = fmaxf(cand[j + 2] - tau_m, 0.f); s2 += c2 * c2 * c2;
                    float c3 = fmaxf(cand[j + 3] - tau_m, 0.f); s3 += c3 * c3 * c3;
                }
                for (; j < n; ++j) {
                    float c = fmaxf(cand[j] - tau_m, 0.f); s0 += c * c * c;
                }
                float s = (s0 + s1) + (s2 + s3);
                if (s >= 1.0f) tau_lo = tau_m;   // f_m = s - 1 >= 0 (exact near 1 by Sterbenz)
            }
            float S0 = 0.f, S1 = 0.f;
            for (int j = 0; j < n; ++j) {
                float c = fmaxf(cand[j] - tau_m, 0.f);
                if (j & 1) S1 += c * c; else S0 += c * c;
            }
            if (t == 0) { s_tau = tau_m; s_invS = 1.0f / (S0 + S1); }
        } else {
            // Fallback (statistically never): dense scan of the SMEM row.
            // Non-candidates contribute exactly 0, so the sums are identical.
            for (int it = 0; it < 50; ++it) {
                dm *= 0.5f;
                tau_m = tau_lo + dm;
                if (tau_m == tau_lo) break;
                float s = 0.f;
                for (int j = t; j < D; j += 32) {
                    float c = fmaxf(row[j] - tau_m, 0.f); s += c * c * c;
                }
#pragma unroll
                for (int o = 16; o; o >>= 1) s += __shfl_xor_sync(0xffffffffu, s, o);
                if (s >= 1.0f) tau_lo = tau_m;
            }
            float S = 0.f;
            for (int j = t; j < D; j += 32) {
                float c = fmaxf(row[j] - tau_m, 0.f); S += c * c;
            }
#pragma unroll
            for (int o = 16; o; o >>= 1) S += __shfl_xor_sync(0xffffffffu, S, o);
            if (t == 0) { s_tau = tau_m; s_invS = 1.0f / S; }
        }
    }
    __syncthreads();

    // ---- Pass 4: write output from SMEM row ----
    const float tau  = s_tau;
    const float invS = s_invS;
#pragma unroll
    for (int k = 0; k < F4S; ++k) {
        float4 v = rowv[t + k * THREADS];
        float4 o;
        float c;
        c = fmaxf(v.x - tau, 0.f); o.x = c * c * invS;
        c = fmaxf(v.y - tau, 0.f); o.y = c * c * invS;
        c = fmaxf(v.z - tau, 0.f); o.z = c * c * invS;
        c = fmaxf(v.w - tau, 0.f); o.w = c * c * invS;
        xout[t + k * THREADS] = o;
    }
}

extern "C" void kernel_launch(void* const* d_in, const int* in_sizes, int n_in,
                              void* d_out, int out_size) {
    const float* X = (const float*)d_in[0];
    float* Out = (float*)d_out;
    int nrows = out_size / D;
    normmax_kernel<<<nrows, THREADS>>>(X, Out);
}

// round 2
// speedup vs baseline: 1.5694x; 1.5694x over previous
#include <cuda_runtime.h>
#include <float.h>

// NormmaxBisect, alpha = 1.5, n_iter = 50, d = 2048.
// p = max(x - tau, 0)^2 ; p^alpha = max(x - tau, 0)^3.
// tau in (max-1, max - d^-0.5], so only elements with x > max-1 matter.
// Output is 0 everywhere except those ~14 candidates -> zero-fill + scatter.

constexpr int   D        = 2048;
constexpr int   THREADS  = 128;
constexpr int   F4S      = D / 4 / THREADS;          // 4 float4 per thread
constexpr int   CAND_CAP = 192;
constexpr int   KMAX     = CAND_CAP / 32;            // 6
constexpr float TAU_HI_OFF = 0.022097086912079612f;  // (1/2048)^0.5

__global__ void __launch_bounds__(THREADS)
normmax_kernel(const float* __restrict__ X, float* __restrict__ Out)
{
    __shared__ float s_cand[CAND_CAP];
    __shared__ int   s_pos[CAND_CAP];
    __shared__ float s_red[THREADS / 32];
    __shared__ float s_red2[THREADS / 32];
    __shared__ int   s_cnt;
    __shared__ float s_tau, s_invS;

    const size_t base = (size_t)blockIdx.x * D;
    const float4* __restrict__ xin  = reinterpret_cast<const float4*>(X + base);
    float4* __restrict__       xout = reinterpret_cast<float4*>(Out + base);

    const int t    = threadIdx.x;
    const int lane = t & 31;
    const int wid  = t >> 5;
    if (t == 0) s_cnt = 0;

    // ---- Pass 1: load row into registers, start zero-fill, compute max ----
    float4 v[F4S];
    float  m = -FLT_MAX;
#pragma unroll
    for (int k = 0; k < F4S; ++k) {
        v[k] = xin[t + k * THREADS];
        m = fmaxf(m, fmaxf(fmaxf(v[k].x, v[k].y), fmaxf(v[k].z, v[k].w)));
    }
    // Zero-fill output early: overlaps with everything below (fixed up by scatter).
    const float4 z4 = make_float4(0.f, 0.f, 0.f, 0.f);
#pragma unroll
    for (int k = 0; k < F4S; ++k) xout[t + k * THREADS] = z4;

#pragma unroll
    for (int o = 16; o; o >>= 1)
        m = fmaxf(m, __shfl_xor_sync(0xffffffffu, m, o));
    if (lane == 0) s_red[wid] = m;
    __syncthreads();
    float maxval = fmaxf(fmaxf(s_red[0], s_red[1]), fmaxf(s_red[2], s_red[3]));
    const float thresh = maxval - 1.0f;

    // ---- Pass 2: ballot-compaction gather of candidates (value + position) ----
#pragma unroll
    for (int k = 0; k < F4S; ++k) {
#pragma unroll
        for (int c = 0; c < 4; ++c) {
            float x = (c == 0) ? v[k].x : (c == 1) ? v[k].y : (c == 2) ? v[k].z : v[k].w;
            bool  p = x > thresh;
            unsigned mask = __ballot_sync(0xffffffffu, p);
            if (mask) {  // warp-uniform
                int b;
                if (lane == 0) b = atomicAdd(&s_cnt, __popc(mask));
                b = __shfl_sync(0xffffffffu, b, 0);
                if (p) {
                    int off = b + __popc(mask & ((1u << lane) - 1u));
                    if (off < CAND_CAP) {
                        s_cand[off] = x;
                        s_pos[off]  = 4 * t + 512 * k + c;
                    }
                }
            }
        }
    }
    __syncthreads();
    const int n = s_cnt;

    if (n <= CAND_CAP) {
        // ---- Fast path: lane-parallel bisection in ONE warp,
        //      chosen per-block so bisection load spreads over all 4 SMSPs. ----
        if (wid == (blockIdx.x & 3)) {
            const int K = (n + 31) >> 5;   // candidate regs per lane (usually 1)
            float cv[KMAX];
#pragma unroll
            for (int q = 0; q < KMAX; ++q) {
                int j = lane + 32 * q;
                cv[q] = (j < n) ? s_cand[j] : -1.0e30f;
            }

            float tau_lo = thresh;
            float dm     = (maxval - TAU_HI_OFF) - tau_lo;
            float tau_m  = tau_lo;

            if (K == 1) {
                const float c0 = cv[0];
                for (int it = 0; it < 50; ++it) {
                    dm *= 0.5f;
                    tau_m = tau_lo + dm;
                    if (tau_m == tau_lo) break;   // fp32-frozen; identical result
                    float c = fmaxf(c0 - tau_m, 0.f);
                    float s = c * c * c;
#pragma unroll
                    for (int o = 16; o; o >>= 1) s += __shfl_xor_sync(0xffffffffu, s, o);
                    if (s >= 1.0f) tau_lo = tau_m;
                }
            } else {
                for (int it = 0; it < 50; ++it) {
                    dm *= 0.5f;
                    tau_m = tau_lo + dm;
                    if (tau_m == tau_lo) break;
                    float s = 0.f;
#pragma unroll
                    for (int q = 0; q < KMAX; ++q)
                        if (q < K) {
                            float c = fmaxf(cv[q] - tau_m, 0.f);
                            s = fmaf(c * c, c, s);
                        }
#pragma unroll
                    for (int o = 16; o; o >>= 1) s += __shfl_xor_sync(0xffffffffu, s, o);
                    if (s >= 1.0f) tau_lo = tau_m;
                }
            }

            float S = 0.f;
#pragma unroll
            for (int q = 0; q < KMAX; ++q)
                if (q < K) {
                    float c = fmaxf(cv[q] - tau_m, 0.f);
                    S = fmaf(c, c, S);
                }
#pragma unroll
            for (int o = 16; o; o >>= 1) S += __shfl_xor_sync(0xffffffffu, S, o);
            if (lane == 0) { s_tau = tau_m; s_invS = 1.0f / S; }
        }
        __syncthreads();

        // ---- Scatter the few nonzero outputs ----
        const float tau  = s_tau;
        const float invS = s_invS;
        for (int j = t; j < n; j += THREADS) {
            float c = fmaxf(s_cand[j] - tau, 0.f);
            Out[base + s_pos[j]] = c * c * invS;
        }
    } else {
        // ---- Dense fallback (statistically never): all threads, row in regs ----
        float tau_lo = thresh;
        float dm     = (maxval - TAU_HI_OFF) - tau_lo;
        float tau_m  = tau_lo;
        for (int it = 0; it < 50; ++it) {
            dm *= 0.5f;
            tau_m = tau_lo + dm;
            if (tau_m == tau_lo) break;   // uniform across block
            float s = 0.f;
#pragma unroll
            for (int k = 0; k < F4S; ++k) {
                float c;
                c = fmaxf(v[k].x - tau_m, 0.f); s = fmaf(c * c, c, s);
                c = fmaxf(v[k].y - tau_m, 0.f); s = fmaf(c * c, c, s);
                c = fmaxf(v[k].z - tau_m, 0.f); s = fmaf(c * c, c, s);
                c = fmaxf(v[k].w - tau_m, 0.f); s = fmaf(c * c, c, s);
            }
#pragma unroll
            for (int o = 16; o; o >>= 1) s += __shfl_xor_sync(0xffffffffu, s, o);
            if (lane == 0) s_red2[wid] = s;
            __syncthreads();
            s = (s_red2[0] + s_red2[1]) + (s_red2[2] + s_red2[3]);
            __syncthreads();
            if (s >= 1.0f) tau_lo = tau_m;
        }
        float S = 0.f;
#pragma unroll
        for (int k = 0; k < F4S; ++k) {
            float c;
            c = fmaxf(v[k].x - tau_m, 0.f); S = fmaf(c, c, S);
            c = fmaxf(v[k].y - tau_m, 0.f); S = fmaf(c, c, S);
            c = fmaxf(v[k].z - tau_m, 0.f); S = fmaf(c, c, S);
            c = fmaxf(v[k].w - tau_m, 0.f); S = fmaf(c, c, S);
        }
#pragma unroll
        for (int o = 16; o; o >>= 1) S += __shfl_xor_sync(0xffffffffu, S, o);
        if (lane == 0) s_red2[wid] = S;
        __syncthreads();
        S = (s_red2[0] + s_red2[1]) + (s_red2[2] + s_red2[3]);
        const float invS = 1.0f / S;

#pragma unroll
        for (int k = 0; k < F4S; ++k) {
            float4 o; float c;
            c = fmaxf(v[k].x - tau_m, 0.f); o.x = c * c * invS;
            c = fmaxf(v[k].y - tau_m, 0.f); o.y = c * c * invS;
            c = fmaxf(v[k].z - tau_m, 0.f); o.z = c * c * invS;
            c = fmaxf(v[k].w - tau_m, 0.f); o.w = c * c * invS;
            xout[t + k * THREADS] = o;
        }
    }
}

extern "C" void kernel_launch(void* const* d_in, const int* in_sizes, int n_in,
                              void* d_out, int out_size) {
    const float* X = (const float*)d_in[0];
    float* Out = (float*)d_out;
    int nrows = out_size / D;
    normmax_kernel<<<nrows, THREADS>>>(X, Out);
}

// round 3
// speedup vs baseline: 2.0536x; 1.3085x over previous
#include <cuda_runtime.h>
#include <float.h>

// NormmaxBisect, alpha = 1.5, n_iter = 50, d = 2048.
// p = max(x - tau, 0)^2 ; p^alpha = max(x - tau, 0)^3.
// Only elements with x > max-1 can be nonzero. Output = zero-fill + scatter.
// tau* solved by Newton on f(tau) = sum c^3 - 1 (convex, decreasing) instead of
// 50-step bisection: both land within ~1 ulp of the same fp32 root.

constexpr int   D       = 2048;
constexpr int   THREADS = 256;
constexpr int   CAP     = 128;                        // >> E[#candidates] ~ 14
constexpr float TAU_HI_OFF = 0.022097086912079612f;   // (1/2048)^0.5
constexpr int   NEWTON_ITERS = 8;

__global__ void __launch_bounds__(THREADS)
normmax_kernel(const float* __restrict__ X, float* __restrict__ Out)
{
    __shared__ float s_cand[CAP];
    __shared__ int   s_pos[CAP];
    __shared__ float s_red[THREADS / 32];
    __shared__ int   s_cnt;

    const size_t base = (size_t)blockIdx.x * D;
    const float4* __restrict__ xin  = reinterpret_cast<const float4*>(X + base);
    float4* __restrict__       xout = reinterpret_cast<float4*>(Out + base);

    const int t    = threadIdx.x;
    const int lane = t & 31;
    const int wid  = t >> 5;
    if (t == 0) s_cnt = 0;

    // ---- Load 8 elems/thread, zero-fill output early, block max ----
    float4 v0 = xin[t];
    float4 v1 = xin[t + THREADS];
    const float4 z4 = make_float4(0.f, 0.f, 0.f, 0.f);
    xout[t]           = z4;
    xout[t + THREADS] = z4;

    float x0 = v0.x, x1 = v0.y, x2 = v0.z, x3 = v0.w;
    float x4 = v1.x, x5 = v1.y, x6 = v1.z, x7 = v1.w;

    float m = fmaxf(fmaxf(fmaxf(x0, x1), fmaxf(x2, x3)),
                    fmaxf(fmaxf(x4, x5), fmaxf(x6, x7)));
#pragma unroll
    for (int o = 16; o; o >>= 1)
        m = fmaxf(m, __shfl_xor_sync(0xffffffffu, m, o));
    if (lane == 0) s_red[wid] = m;
    __syncthreads();

    float maxval = s_red[0];
#pragma unroll
    for (int w = 1; w < THREADS / 32; ++w) maxval = fmaxf(maxval, s_red[w]);
    const float thresh = maxval - 1.0f;

    // ---- Gather candidates: per-thread bitmask, no ballots ----
    unsigned mm = 0;
    mm |= (x0 > thresh) ? 1u   : 0u;
    mm |= (x1 > thresh) ? 2u   : 0u;
    mm |= (x2 > thresh) ? 4u   : 0u;
    mm |= (x3 > thresh) ? 8u   : 0u;
    mm |= (x4 > thresh) ? 16u  : 0u;
    mm |= (x5 > thresh) ? 32u  : 0u;
    mm |= (x6 > thresh) ? 64u  : 0u;
    mm |= (x7 > thresh) ? 128u : 0u;
    if (mm) {   // ~5% of threads
        int p = atomicAdd(&s_cnt, __popc(mm));
        float xv[8] = {x0, x1, x2, x3, x4, x5, x6, x7};
#pragma unroll
        for (int i = 0; i < 8; ++i) {
            if ((mm >> i) & 1) {
                if (p < CAP) {
                    s_cand[p] = xv[i];
                    // element index: float4 slot (t + (i>>2)*THREADS), component i&3
                    s_pos[p]  = 4 * t + (i >> 2) * (4 * THREADS) + (i & 3);
                }
                ++p;
            }
        }
    }
    __syncthreads();
    const int n = s_cnt;

    // Only one warp continues; the rest retire (their zero-fill stores are
    // ordered before the scatter by the barrier above).
    if (wid != (int)(blockIdx.x & (unsigned)(THREADS / 32 - 1))) return;

    if (n <= CAP) {
        // ---- Newton on f(tau) = sum c^3 - 1, lane-parallel over <=128 cands ----
        const float SENT = -1.0e30f;   // contributes exactly 0 through fmaxf
        float cv0 = (lane      < n) ? s_cand[lane]      : SENT;
        float cv1 = (lane + 32 < n) ? s_cand[lane + 32] : SENT;
        float cv2 = (lane + 64 < n) ? s_cand[lane + 64] : SENT;
        float cv3 = (lane + 96 < n) ? s_cand[lane + 96] : SENT;

        const float tau_hi = maxval - TAU_HI_OFF;   // f(tau_hi) < 0 always
        float tau = thresh;                          // f(thresh) >= 0

#pragma unroll
        for (int it = 0; it < NEWTON_ITERS; ++it) {
            float c0 = fmaxf(cv0 - tau, 0.f), q0 = c0 * c0;
            float c1 = fmaxf(cv1 - tau, 0.f), q1 = c1 * c1;
            float c2 = fmaxf(cv2 - tau, 0.f), q2 = c2 * c2;
            float c3 = fmaxf(cv3 - tau, 0.f), q3 = c3 * c3;
            float a = (q0 + q1) + (q2 + q3);                      // sum c^2
            float b = fmaf(q0, c0, fmaf(q1, c1, fmaf(q2, c2, q3 * c3)));  // sum c^3
#pragma unroll
            for (int o = 16; o; o >>= 1) {  // two independent chains, pipelined
                a += __shfl_xor_sync(0xffffffffu, a, o);
                b += __shfl_xor_sync(0xffffffffu, b, o);
            }
            // f = b - 1, f' = -3a  (a >= (maxval-tau)^2 > 0 since tau <= tau_hi)
            tau += (b - 1.0f) / (3.0f * a);
            tau = fminf(fmaxf(tau, thresh), tau_hi);
        }

        // ---- Final S = sum c^2 and scatter (this warp only) ----
        float c0 = fmaxf(cv0 - tau, 0.f), q0 = c0 * c0;
        float c1 = fmaxf(cv1 - tau, 0.f), q1 = c1 * c1;
        float c2 = fmaxf(cv2 - tau, 0.f), q2 = c2 * c2;
        float c3 = fmaxf(cv3 - tau, 0.f), q3 = c3 * c3;
        float S = (q0 + q1) + (q2 + q3);
#pragma unroll
        for (int o = 16; o; o >>= 1) S += __shfl_xor_sync(0xffffffffu, S, o);
        const float invS = 1.0f / S;

        if (lane      < n) Out[base + s_pos[lane]]      = q0 * invS;
        if (lane + 32 < n) Out[base + s_pos[lane + 32]] = q1 * invS;
        if (lane + 64 < n) Out[base + s_pos[lane + 64]] = q2 * invS;
        if (lane + 96 < n) Out[base + s_pos[lane + 96]] = q3 * invS;
    } else {
        // ---- Dense fallback (statistically never): exact reference bisection,
        //      single warp, row re-read through L1/L2. ----
        float tau_lo = thresh;
        float dm     = (maxval - TAU_HI_OFF) - tau_lo;
        float tau_m  = tau_lo;
        for (int it = 0; it < 50; ++it) {
            dm *= 0.5f;
            tau_m = tau_lo + dm;
            if (tau_m == tau_lo) break;
            float s = 0.f;
            for (int j = lane; j < D; j += 32) {
                float c = fmaxf(X[base + j] - tau_m, 0.f);
                s = fmaf(c * c, c, s);
            }
#pragma unroll
            for (int o = 16; o; o >>= 1) s += __shfl_xor_sync(0xffffffffu, s, o);
            if (s >= 1.0f) tau_lo = tau_m;
        }
        float S = 0.f;
        for (int j = lane; j < D; j += 32) {
            float c = fmaxf(X[base + j] - tau_m, 0.f);
            S = fmaf(c, c, S);
        }
#pragma unroll
        for (int o = 16; o; o >>= 1) S += __shfl_xor_sync(0xffffffffu, S, o);
        const float invS = 1.0f / S;
        for (int j = lane; j < D; j += 32) {
            float c = fmaxf(X[base + j] - tau_m, 0.f);
            Out[base + j] = c * c * invS;
        }
    }
}

extern "C" void kernel_launch(void* const* d_in, const int* in_sizes, int n_in,
                              void* d_out, int out_size) {
    const float* X = (const float*)d_in[0];
    float* Out = (float*)d_out;
    int nrows = out_size / D;
    normmax_kernel<<<nrows, THREADS>>>(X, Out);
}